// round 7
// baseline (speedup 1.0000x reference)
#include <cuda_runtime.h>
#include <cuda_bf16.h>
#include <stdint.h>

#define NN 8192
#define DD 128
#define KK 4096         // K = N/2
#define NKEEP (NN - KK) // 4096
#define WPR 256         // 32-bit words per adjacency row
#define NB  512         // persistent grid size (must be wave-1 co-resident)

typedef unsigned long long u64;
typedef unsigned int u32;

// ---------------- device scratch ------------------------------------------
__device__ u32   g_adj[NN * WPR];   // adjacency bitmap, 8MB; zero on entry
__device__ u32   g_adj2[NN * 8];    // summary: bit w => adj word w nonzero; zero on entry
__device__ int   g_deg[NN];         // zero on entry
__device__ int   g_rank[NN];        // zeroed in phase B before phase C atomics
__device__ float g_norm[NN];
__device__ float g_wf[NN];
__device__ u32   g_mw[NN];          // ascending key: smaller = higher weight
__device__ int   g_ei[NN];
__device__ int   g_ej[NN];
__device__ int   g_is64;
__device__ u32   g_barcnt;          // grid barrier state (persistent across replays)
__device__ u32   g_bargen;

// software grid barrier: all NB blocks must be co-resident (guaranteed by
// __launch_bounds__(256,4) resource limits: 512 < 4*148 wave-1 capacity)
__device__ __forceinline__ void grid_barrier() {
    __syncthreads();
    __threadfence();
    if (threadIdx.x == 0) {
        u32 gen = ((volatile u32*)&g_bargen)[0];
        if (atomicAdd(&g_barcnt, 1u) == NB - 1) {
            atomicExch(&g_barcnt, 0u);
            __threadfence();
            atomicAdd(&g_bargen, 1u);              // release
        } else {
            while (((volatile u32*)&g_bargen)[0] == gen) __nanosleep(32);
        }
    }
    __syncthreads();
}

__global__ void __launch_bounds__(256, 4)
mega_kernel(const float* __restrict__ x,
            const void* __restrict__ edges,
            const void* __restrict__ batch,
            float* __restrict__ out) {
    __shared__ union {
        u64 sk[512];                                  // phase C: key chunk
        struct { u32 words[256]; int wpref[256]; int warpsum[8]; } em;  // phase D emit
    } sh;

    int tid  = threadIdx.x;
    int wid  = tid >> 5;
    int lane = tid & 31;

    // ================= Phase A: norms + edge decode + bitmap + deg ========
    #pragma unroll
    for (int rep = 0; rep < 2; rep++) {
        int row = rep * 4096 + blockIdx.x * 8 + wid;
        const float4* rp = (const float4*)(x + (size_t)row * DD);
        float4 v = rp[lane];
        double s = (double)v.x * v.x + (double)v.y * v.y + (double)v.z * v.z + (double)v.w * v.w;
        #pragma unroll
        for (int o = 16; o > 0; o >>= 1) s += __shfl_down_sync(0xffffffffu, s, o);
        if (lane == 0) g_norm[row] = (float)sqrt(s);
    }

    if (blockIdx.x < 32) {
        // per-warp dtype detect: odd 32-bit words of first 64 entries all zero <=> int64
        const u32* e32 = (const u32*)edges;
        u32 odd = e32[2 * lane + 1] | e32[2 * (lane + 32) + 1];
        int is64 = !__any_sync(0xffffffffu, odd != 0u);
        if (blockIdx.x == 0 && tid == 0) g_is64 = is64;

        int e = blockIdx.x * 256 + tid;
        int i, j;
        if (is64) {
            const long long* p = (const long long*)edges;
            i = (int)p[e];
            j = (int)p[NN + e];
        } else {
            const int* p = (const int*)edges;
            i = p[e];
            j = p[NN + e];
        }
        g_ei[e] = i;
        g_ej[e] = j;
        u32 bit = 1u << (j & 31);
        u32 old = atomicOr(&g_adj[i * WPR + (j >> 5)], bit);
        if (!(old & bit)) atomicAdd(&g_deg[i], 1);   // unique edge: deterministic
        atomicOr(&g_adj2[i * 8 + (j >> 10)], 1u << ((j >> 5) & 31));
    }

    grid_barrier();

    // ================= Phase B: weights (deterministic j-asc order) =======
    #pragma unroll
    for (int rep = 0; rep < 2; rep++) {
        int node = rep * 4096 + blockIdx.x * 8 + wid;

        float ni = fmaxf(g_norm[node], 1e-12f);
        float4 a = ((const float4*)(x + (size_t)node * DD))[lane];
        float ax = a.x / ni, ay = a.y / ni, az = a.z / ni, aw = a.w / ni;

        double acc = 0.0;
        u32 sum_w = (lane < 8) ? g_adj2[node * 8 + lane] : 0u;
        u32 sm = __ballot_sync(0xffffffffu, sum_w != 0u);     // bits 0..7
        while (sm) {                                          // ascending summary word
            int sw = __ffs(sm) - 1;
            sm &= sm - 1;
            u32 swbits = __shfl_sync(0xffffffffu, sum_w, sw);
            while (swbits) {                                  // ascending adj word
                int wb = __ffs(swbits) - 1;
                swbits &= swbits - 1;
                int w = sw * 32 + wb;                         // 0..255
                u32 bits = g_adj[node * WPR + w];             // uniform -> broadcast
                int jbase = w * 32;
                while (bits) {                                // ascending j
                    int b = __ffs(bits) - 1;
                    bits &= bits - 1;
                    int j = jbase + b;
                    float nj = fmaxf(g_norm[j], 1e-12f);
                    float4 bv = ((const float4*)(x + (size_t)j * DD))[lane];
                    float bx = bv.x / nj, by = bv.y / nj, bz = bv.z / nj, bw = bv.w / nj;
                    double s = (double)ax * bx + (double)ay * by + (double)az * bz + (double)aw * bw;
                    #pragma unroll
                    for (int o = 16; o > 0; o >>= 1) s += __shfl_down_sync(0xffffffffu, s, o);
                    if (lane == 0) {
                        int dj = g_deg[j];
                        float dinvj = (dj > 0) ? (float)(1.0 / sqrt((double)dj)) : 0.0f;
                        acc += s * (double)dinvj;             // identical numerics to R3-R6
                    }
                }
            }
        }
        if (lane == 0) {
            int dn = g_deg[node];
            float dinvn = (dn > 0) ? (float)(1.0 / sqrt((double)dn)) : 0.0f;
            float wf = (float)((double)dinvn * acc);
            g_wf[node] = wf;
            u32 u = __float_as_uint(wf);
            u32 m = (u & 0x80000000u) ? ~u : (u | 0x80000000u);
            g_mw[node] = ~m;       // smaller = larger weight -> rank asc = topk order
            g_rank[node] = 0;      // reset before phase C atomics
        }
    }

    grid_barrier();

    // ================= Phase C: rank = #{keys < mine} ======================
    {
        int bn = blockIdx.x & 31;          // node chunk (256 nodes)
        int bj = blockIdx.x >> 5;          // key chunk (512 keys)
        int jbase = bj * 512;
        #pragma unroll
        for (int q = 0; q < 2; q++) {
            int i = tid + q * 256;
            int j = jbase + i;
            sh.sk[i] = ((u64)g_mw[j] << 13) | (u32)j;
        }
        __syncthreads();

        int node = bn * 256 + tid;
        u64 my = ((u64)g_mw[node] << 13) | (u32)node;
        int cnt = 0;
        const ulonglong2* sk2 = (const ulonglong2*)sh.sk;
        #pragma unroll 8
        for (int i = 0; i < 256; i++) {
            ulonglong2 p = sk2[i];
            cnt += (p.x < my) + (p.y < my);
        }
        atomicAdd(&g_rank[node], cnt);     // integer: deterministic
    }

    grid_barrier();

    // ================= Phase D: gather + emit + invariant restore =========
    // gather: warp per node; output row == rank
    #pragma unroll
    for (int rep = 0; rep < 2; rep++) {
        int node = rep * 4096 + blockIdx.x * 8 + wid;
        int r = g_rank[node];
        if (r < KK) {
            float4 v = ((const float4*)(x + (size_t)node * DD))[lane];
            ((float4*)(out + (size_t)r * DD))[lane] = v;
            if (lane == 0) {
                const int OFF_PERM  = KK * DD + 2 * NKEEP;
                const int OFF_BATCH = OFF_PERM + KK;
                const int OFF_W     = OFF_BATCH + KK;
                long long bv;
                if (g_is64) bv = ((const long long*)batch)[node];
                else        bv = (long long)((const int*)batch)[node];
                out[OFF_PERM + r]  = (float)node;
                out[OFF_BATCH + r] = (float)bv;
                out[OFF_W + r]     = g_wf[node];
            }
        }
    }

    // emit: blocks 0..31 (unselected-bitmap + popcount prefix)
    if (blockIdx.x < 32) {
        #pragma unroll
        for (int q = 0; q < 32; q++) {
            int n2 = q * 256 + tid;
            int uns = (g_rank[n2] >= KK) ? 1 : 0;
            u32 w = __ballot_sync(0xffffffffu, uns);
            if (lane == 0) sh.em.words[q * 8 + wid] = w;
        }
        __syncthreads();

        int c = __popc(sh.em.words[tid]);
        int v = c;
        #pragma unroll
        for (int o = 1; o < 32; o <<= 1) {
            int t = __shfl_up_sync(0xffffffffu, v, o);
            if (lane >= o) v += t;
        }
        if (lane == 31) sh.em.warpsum[wid] = v;
        __syncthreads();
        if (wid == 0) {
            int s = (lane < 8) ? sh.em.warpsum[lane] : 0;
            #pragma unroll
            for (int o = 1; o < 8; o <<= 1) {
                int t = __shfl_up_sync(0xffffffffu, s, o);
                if (lane >= o) s += t;
            }
            if (lane < 8) sh.em.warpsum[lane] = s;
        }
        __syncthreads();
        sh.em.wpref[tid] = v - c + ((wid > 0) ? sh.em.warpsum[wid - 1] : 0);
        __syncthreads();

        int i = blockIdx.x * 256 + tid;
        if (g_rank[i] >= KK) {               // kept edge slot
            int word = i >> 5;
            u32 w = sh.em.words[word];
            int pos = sh.em.wpref[word] + __popc(w & ((1u << (i & 31)) - 1u));
            int a = g_ei[i], b = g_ej[i];
            int ra = g_rank[a], rb = g_rank[b];
            const int OFF_E = KK * DD;
            out[OFF_E + pos]         = (float)((ra < KK) ? ra : 0);
            out[OFF_E + NKEEP + pos] = (float)((rb < KK) ? rb : 0);
        }
    }

    // restore zero-invariants: blocks 480..511
    if (blockIdx.x >= NB - 32) {
        int e = (blockIdx.x - (NB - 32)) * 256 + tid;
        int a = g_ei[e], b = g_ej[e];
        g_adj[a * WPR + (b >> 5)] = 0u;
        g_adj2[a * 8 + (b >> 10)] = 0u;
        g_deg[e] = 0;
    }
}

// ---------------- launch ----------------
extern "C" void kernel_launch(void* const* d_in, const int* in_sizes, int n_in,
                              void* d_out, int out_size) {
    const float* x     = (const float*)d_in[0];
    const void*  edges = d_in[1];
    const void*  batch = d_in[2];
    float* out = (float*)d_out;

    mega_kernel<<<NB, 256>>>(x, edges, batch, out);
}